// round 10
// baseline (speedup 1.0000x reference)
#include <cuda_runtime.h>

// 3-level non-overlapping 2D Haar DWT, fully fused, single kernel. (FINAL: R4 config)
// x: (16, 64, 256, 256) fp32. Filter len 2, stride 2 => each 8x8 input block
// independently produces: 4x4 of (lh1,hl1,hh1), 2x2 of (lh2,hl2,hh2),
// 1x1 of (l3,lh3,hl3,hh3). Edge-pad is a no-op (all dims even).
//
// Output flat order (pytree flatten of (l,(lh3,hl3,hh3),(lh2,hl2,hh2),(lh1,hl1,hh1))):
//   l3  @ 0         lh3 @ 1048576   hl3 @ 2097152   hh3 @ 3145728
//   lh2 @ 4194304   hl2 @ 8388608   hh2 @ 12582912
//   lh1 @ 16777216  hl1 @ 33554432  hh1 @ 50331648
//   total = 67108864 = out_size
//
// Measured optimum: bench 82.43us, kernel 75.8-76.4us, DRAM 80-81% (6.35-6.40 TB/s).
// Traffic is at the information floor (268MB read + 268MB write, fully coalesced).
// Tested and rejected in isolation: higher occupancy (neutral), persistent
// single-wave grid (regress, serializes MLP), __ldcs loads (regress, reg
// explosion), __stcs stores (regress, loses L2 write buffering). This kernel
// sits at the mixed-R/W HBM roofline.

__global__ __launch_bounds__(256) void dwt3_fused_kernel(
    const float* __restrict__ x,
    const float* __restrict__ dec_lo,
    const float* __restrict__ dec_hi,
    float* __restrict__ out)
{
    const float lo0 = dec_lo[0], lo1 = dec_lo[1];
    const float hi0 = dec_hi[0], hi1 = dec_hi[1];

    const unsigned tid = blockIdx.x * blockDim.x + threadIdx.x;
    const unsigned bx = tid & 31u;          // 8x8 block col within plane (32 blocks)
    const unsigned by = (tid >> 5) & 31u;   // 8x8 block row within plane
    const unsigned bc = tid >> 10;          // plane index b*64+c in [0,1024)

    const float* plane = x + (size_t)bc * 65536u + (size_t)(by * 8u) * 256u + bx * 8u;

    // ---- front-batch all 16 input loads (8 rows x 2 float4) for max MLP ----
    float4 v[8][2];
    #pragma unroll
    for (int r = 0; r < 8; r++) {
        const float* p = plane + (size_t)r * 256u;
        v[r][0] = __ldg((const float4*)p);
        v[r][1] = __ldg((const float4*)(p + 4));
    }

    float ll1[4][4];

    // ---------------- level 1 ----------------
    float* lh1 = out + 16777216u + (size_t)bc * 16384u + (size_t)(by * 4u) * 128u + bx * 4u;
    float* hl1 = lh1 + 16777216u;
    float* hh1 = hl1 + 16777216u;

    #pragma unroll
    for (int r = 0; r < 4; r++) {
        float A[8]  = {v[2*r][0].x,   v[2*r][0].y,   v[2*r][0].z,   v[2*r][0].w,
                       v[2*r][1].x,   v[2*r][1].y,   v[2*r][1].z,   v[2*r][1].w};
        float Bv[8] = {v[2*r+1][0].x, v[2*r+1][0].y, v[2*r+1][0].z, v[2*r+1][0].w,
                       v[2*r+1][1].x, v[2*r+1][1].y, v[2*r+1][1].z, v[2*r+1][1].w};
        float lh[4], hl[4], hh[4];
        #pragma unroll
        for (int c = 0; c < 4; c++) {
            float alo = lo0 * A[2*c]  + lo1 * A[2*c+1];
            float ahi = hi0 * A[2*c]  + hi1 * A[2*c+1];
            float blo = lo0 * Bv[2*c] + lo1 * Bv[2*c+1];
            float bhi = hi0 * Bv[2*c] + hi1 * Bv[2*c+1];
            ll1[r][c] = lo0 * alo + lo1 * blo;   // LL -> level 2
            lh[c]     = hi0 * alo + hi1 * blo;   // filt[1] = outer(hi, lo)
            hl[c]     = lo0 * ahi + lo1 * bhi;   // filt[2] = outer(lo, hi)
            hh[c]     = hi0 * ahi + hi1 * bhi;   // filt[3] = outer(hi, hi)
        }
        *((float4*)(lh1 + r * 128)) = make_float4(lh[0], lh[1], lh[2], lh[3]);
        *((float4*)(hl1 + r * 128)) = make_float4(hl[0], hl[1], hl[2], hl[3]);
        *((float4*)(hh1 + r * 128)) = make_float4(hh[0], hh[1], hh[2], hh[3]);
    }

    // ---------------- level 2 ----------------
    float ll2[2][2];
    float* lh2 = out + 4194304u + (size_t)bc * 4096u + (size_t)(by * 2u) * 64u + bx * 2u;
    float* hl2 = lh2 + 4194304u;
    float* hh2 = hl2 + 4194304u;

    #pragma unroll
    for (int r = 0; r < 2; r++) {
        float lh[2], hl[2], hh[2];
        #pragma unroll
        for (int c = 0; c < 2; c++) {
            float x00 = ll1[2*r][2*c],   x01 = ll1[2*r][2*c+1];
            float x10 = ll1[2*r+1][2*c], x11 = ll1[2*r+1][2*c+1];
            float alo = lo0 * x00 + lo1 * x01;
            float ahi = hi0 * x00 + hi1 * x01;
            float blo = lo0 * x10 + lo1 * x11;
            float bhi = hi0 * x10 + hi1 * x11;
            ll2[r][c] = lo0 * alo + lo1 * blo;
            lh[c]     = hi0 * alo + hi1 * blo;
            hl[c]     = lo0 * ahi + lo1 * bhi;
            hh[c]     = hi0 * ahi + hi1 * bhi;
        }
        *((float2*)(lh2 + r * 64)) = make_float2(lh[0], lh[1]);
        *((float2*)(hl2 + r * 64)) = make_float2(hl[0], hl[1]);
        *((float2*)(hh2 + r * 64)) = make_float2(hh[0], hh[1]);
    }

    // ---------------- level 3 ----------------
    {
        float x00 = ll2[0][0], x01 = ll2[0][1];
        float x10 = ll2[1][0], x11 = ll2[1][1];
        float alo = lo0 * x00 + lo1 * x01;
        float ahi = hi0 * x00 + hi1 * x01;
        float blo = lo0 * x10 + lo1 * x11;
        float bhi = hi0 * x10 + hi1 * x11;
        size_t o3 = (size_t)bc * 1024u + by * 32u + bx;
        out[o3]             = lo0 * alo + lo1 * blo;  // l3 (final approx)
        out[1048576u + o3]  = hi0 * alo + hi1 * blo;  // lh3
        out[2097152u + o3]  = lo0 * ahi + lo1 * bhi;  // hl3
        out[3145728u + o3]  = hi0 * ahi + hi1 * bhi;  // hh3
    }
}

extern "C" void kernel_launch(void* const* d_in, const int* in_sizes, int n_in,
                              void* d_out, int out_size) {
    const float* x      = (const float*)d_in[0];
    const float* dec_lo = (const float*)d_in[1];
    const float* dec_hi = (const float*)d_in[2];
    float* out = (float*)d_out;

    // 16*64 planes * 32*32 blocks of 8x8 = 1,048,576 threads
    dwt3_fused_kernel<<<4096, 256>>>(x, dec_lo, dec_hi, out);
}

// round 11
// speedup vs baseline: 1.0109x; 1.0109x over previous
#include <cuda_runtime.h>

// 3-level non-overlapping 2D Haar DWT, fully fused, single kernel. (FINAL)
// x: (16, 64, 256, 256) fp32. Filter len 2, stride 2 => each 8x8 input block
// independently produces: 4x4 of (lh1,hl1,hh1), 2x2 of (lh2,hl2,hh2),
// 1x1 of (l3,lh3,hl3,hh3). Edge-pad is a no-op (all dims even).
//
// Output flat order (pytree flatten of (l,(lh3,hl3,hh3),(lh2,hl2,hh2),(lh1,hl1,hh1))):
//   l3  @ 0         lh3 @ 1048576   hl3 @ 2097152   hh3 @ 3145728
//   lh2 @ 4194304   hl2 @ 8388608   hh2 @ 12582912
//   lh1 @ 16777216  hl1 @ 33554432  hh1 @ 50331648
//   total = 67108864 = out_size
//
// Measured optimum (3x reproduced): kernel 75.8-76.4us, DRAM 80-81%
// (6.35-6.40 TB/s). Traffic at the information floor (268MB read + 268MB
// write, fully coalesced, single pass). Rejected in isolation: higher
// occupancy (neutral 21%-56%), persistent single-wave (+8us, serializes
// per-thread MLP), __ldcs loads (+1.4us, regs 54->86), __stcs stores
// (+1.1us, loses L2 write buffering). At the mixed-R/W HBM roofline.

__global__ __launch_bounds__(256) void dwt3_fused_kernel(
    const float* __restrict__ x,
    const float* __restrict__ dec_lo,
    const float* __restrict__ dec_hi,
    float* __restrict__ out)
{
    const float lo0 = dec_lo[0], lo1 = dec_lo[1];
    const float hi0 = dec_hi[0], hi1 = dec_hi[1];

    const unsigned tid = blockIdx.x * blockDim.x + threadIdx.x;
    const unsigned bx = tid & 31u;          // 8x8 block col within plane (32 blocks)
    const unsigned by = (tid >> 5) & 31u;   // 8x8 block row within plane
    const unsigned bc = tid >> 10;          // plane index b*64+c in [0,1024)

    const float* plane = x + (size_t)bc * 65536u + (size_t)(by * 8u) * 256u + bx * 8u;

    // ---- front-batch all 16 input loads (8 rows x 2 float4) for max MLP ----
    float4 v[8][2];
    #pragma unroll
    for (int r = 0; r < 8; r++) {
        const float* p = plane + (size_t)r * 256u;
        v[r][0] = __ldg((const float4*)p);
        v[r][1] = __ldg((const float4*)(p + 4));
    }

    float ll1[4][4];

    // ---------------- level 1 ----------------
    float* lh1 = out + 16777216u + (size_t)bc * 16384u + (size_t)(by * 4u) * 128u + bx * 4u;
    float* hl1 = lh1 + 16777216u;
    float* hh1 = hl1 + 16777216u;

    #pragma unroll
    for (int r = 0; r < 4; r++) {
        float A[8]  = {v[2*r][0].x,   v[2*r][0].y,   v[2*r][0].z,   v[2*r][0].w,
                       v[2*r][1].x,   v[2*r][1].y,   v[2*r][1].z,   v[2*r][1].w};
        float Bv[8] = {v[2*r+1][0].x, v[2*r+1][0].y, v[2*r+1][0].z, v[2*r+1][0].w,
                       v[2*r+1][1].x, v[2*r+1][1].y, v[2*r+1][1].z, v[2*r+1][1].w};
        float lh[4], hl[4], hh[4];
        #pragma unroll
        for (int c = 0; c < 4; c++) {
            float alo = lo0 * A[2*c]  + lo1 * A[2*c+1];
            float ahi = hi0 * A[2*c]  + hi1 * A[2*c+1];
            float blo = lo0 * Bv[2*c] + lo1 * Bv[2*c+1];
            float bhi = hi0 * Bv[2*c] + hi1 * Bv[2*c+1];
            ll1[r][c] = lo0 * alo + lo1 * blo;   // LL -> level 2
            lh[c]     = hi0 * alo + hi1 * blo;   // filt[1] = outer(hi, lo)
            hl[c]     = lo0 * ahi + lo1 * bhi;   // filt[2] = outer(lo, hi)
            hh[c]     = hi0 * ahi + hi1 * bhi;   // filt[3] = outer(hi, hi)
        }
        *((float4*)(lh1 + r * 128)) = make_float4(lh[0], lh[1], lh[2], lh[3]);
        *((float4*)(hl1 + r * 128)) = make_float4(hl[0], hl[1], hl[2], hl[3]);
        *((float4*)(hh1 + r * 128)) = make_float4(hh[0], hh[1], hh[2], hh[3]);
    }

    // ---------------- level 2 ----------------
    float ll2[2][2];
    float* lh2 = out + 4194304u + (size_t)bc * 4096u + (size_t)(by * 2u) * 64u + bx * 2u;
    float* hl2 = lh2 + 4194304u;
    float* hh2 = hl2 + 4194304u;

    #pragma unroll
    for (int r = 0; r < 2; r++) {
        float lh[2], hl[2], hh[2];
        #pragma unroll
        for (int c = 0; c < 2; c++) {
            float x00 = ll1[2*r][2*c],   x01 = ll1[2*r][2*c+1];
            float x10 = ll1[2*r+1][2*c], x11 = ll1[2*r+1][2*c+1];
            float alo = lo0 * x00 + lo1 * x01;
            float ahi = hi0 * x00 + hi1 * x01;
            float blo = lo0 * x10 + lo1 * x11;
            float bhi = hi0 * x10 + hi1 * x11;
            ll2[r][c] = lo0 * alo + lo1 * blo;
            lh[c]     = hi0 * alo + hi1 * blo;
            hl[c]     = lo0 * ahi + lo1 * bhi;
            hh[c]     = hi0 * ahi + hi1 * bhi;
        }
        *((float2*)(lh2 + r * 64)) = make_float2(lh[0], lh[1]);
        *((float2*)(hl2 + r * 64)) = make_float2(hl[0], hl[1]);
        *((float2*)(hh2 + r * 64)) = make_float2(hh[0], hh[1]);
    }

    // ---------------- level 3 ----------------
    {
        float x00 = ll2[0][0], x01 = ll2[0][1];
        float x10 = ll2[1][0], x11 = ll2[1][1];
        float alo = lo0 * x00 + lo1 * x01;
        float ahi = hi0 * x00 + hi1 * x01;
        float blo = lo0 * x10 + lo1 * x11;
        float bhi = hi0 * x10 + hi1 * x11;
        size_t o3 = (size_t)bc * 1024u + by * 32u + bx;
        out[o3]             = lo0 * alo + lo1 * blo;  // l3 (final approx)
        out[1048576u + o3]  = hi0 * alo + hi1 * blo;  // lh3
        out[2097152u + o3]  = lo0 * ahi + lo1 * bhi;  // hl3
        out[3145728u + o3]  = hi0 * ahi + hi1 * bhi;  // hh3
    }
}

extern "C" void kernel_launch(void* const* d_in, const int* in_sizes, int n_in,
                              void* d_out, int out_size) {
    const float* x      = (const float*)d_in[0];
    const float* dec_lo = (const float*)d_in[1];
    const float* dec_hi = (const float*)d_in[2];
    float* out = (float*)d_out;

    // 16*64 planes * 32*32 blocks of 8x8 = 1,048,576 threads
    dwt3_fused_kernel<<<4096, 256>>>(x, dec_lo, dec_hi, out);
}

// round 12
// speedup vs baseline: 1.0120x; 1.0012x over previous
#include <cuda_runtime.h>

// 3-level non-overlapping 2D Haar DWT, fully fused, single kernel.
// x: (16, 64, 256, 256) fp32. Filter len 2, stride 2 => each 8x8 input block
// independently produces: 4x4 of (lh1,hl1,hh1), 2x2 of (lh2,hl2,hh2),
// 1x1 of (l3,lh3,hl3,hh3). Edge-pad is a no-op (all dims even).
//
// Output flat order:
//   l3  @ 0         lh3 @ 1048576   hl3 @ 2097152   hh3 @ 3145728
//   lh2 @ 4194304   hl2 @ 8388608   hh2 @ 12582912
//   lh1 @ 16777216  hl1 @ 33554432  hh1 @ 50331648
//
// R12 = R4 structure (4x-reproduced optimum, kernel 75.8-76.5us, DRAM ~80%)
// with the ONLY unswept knob: block size 256 -> 512 (grid 4096 -> 2048).
// Same threads, same addresses, same per-thread code. Probing CTA granularity
// effects on the per-SM LSU/L1tex queue; prior is neutral.

__global__ __launch_bounds__(512) void dwt3_fused_kernel(
    const float* __restrict__ x,
    const float* __restrict__ dec_lo,
    const float* __restrict__ dec_hi,
    float* __restrict__ out)
{
    const float lo0 = dec_lo[0], lo1 = dec_lo[1];
    const float hi0 = dec_hi[0], hi1 = dec_hi[1];

    const unsigned tid = blockIdx.x * blockDim.x + threadIdx.x;
    const unsigned bx = tid & 31u;          // 8x8 block col within plane (32 blocks)
    const unsigned by = (tid >> 5) & 31u;   // 8x8 block row within plane
    const unsigned bc = tid >> 10;          // plane index b*64+c in [0,1024)

    const float* plane = x + (size_t)bc * 65536u + (size_t)(by * 8u) * 256u + bx * 8u;

    // ---- front-batch all 16 input loads (8 rows x 2 float4) for max MLP ----
    float4 v[8][2];
    #pragma unroll
    for (int r = 0; r < 8; r++) {
        const float* p = plane + (size_t)r * 256u;
        v[r][0] = __ldg((const float4*)p);
        v[r][1] = __ldg((const float4*)(p + 4));
    }

    float ll1[4][4];

    // ---------------- level 1 ----------------
    float* lh1 = out + 16777216u + (size_t)bc * 16384u + (size_t)(by * 4u) * 128u + bx * 4u;
    float* hl1 = lh1 + 16777216u;
    float* hh1 = hl1 + 16777216u;

    #pragma unroll
    for (int r = 0; r < 4; r++) {
        float A[8]  = {v[2*r][0].x,   v[2*r][0].y,   v[2*r][0].z,   v[2*r][0].w,
                       v[2*r][1].x,   v[2*r][1].y,   v[2*r][1].z,   v[2*r][1].w};
        float Bv[8] = {v[2*r+1][0].x, v[2*r+1][0].y, v[2*r+1][0].z, v[2*r+1][0].w,
                       v[2*r+1][1].x, v[2*r+1][1].y, v[2*r+1][1].z, v[2*r+1][1].w};
        float lh[4], hl[4], hh[4];
        #pragma unroll
        for (int c = 0; c < 4; c++) {
            float alo = lo0 * A[2*c]  + lo1 * A[2*c+1];
            float ahi = hi0 * A[2*c]  + hi1 * A[2*c+1];
            float blo = lo0 * Bv[2*c] + lo1 * Bv[2*c+1];
            float bhi = hi0 * Bv[2*c] + hi1 * Bv[2*c+1];
            ll1[r][c] = lo0 * alo + lo1 * blo;   // LL -> level 2
            lh[c]     = hi0 * alo + hi1 * blo;   // filt[1] = outer(hi, lo)
            hl[c]     = lo0 * ahi + lo1 * bhi;   // filt[2] = outer(lo, hi)
            hh[c]     = hi0 * ahi + hi1 * bhi;   // filt[3] = outer(hi, hi)
        }
        *((float4*)(lh1 + r * 128)) = make_float4(lh[0], lh[1], lh[2], lh[3]);
        *((float4*)(hl1 + r * 128)) = make_float4(hl[0], hl[1], hl[2], hl[3]);
        *((float4*)(hh1 + r * 128)) = make_float4(hh[0], hh[1], hh[2], hh[3]);
    }

    // ---------------- level 2 ----------------
    float ll2[2][2];
    float* lh2 = out + 4194304u + (size_t)bc * 4096u + (size_t)(by * 2u) * 64u + bx * 2u;
    float* hl2 = lh2 + 4194304u;
    float* hh2 = hl2 + 4194304u;

    #pragma unroll
    for (int r = 0; r < 2; r++) {
        float lh[2], hl[2], hh[2];
        #pragma unroll
        for (int c = 0; c < 2; c++) {
            float x00 = ll1[2*r][2*c],   x01 = ll1[2*r][2*c+1];
            float x10 = ll1[2*r+1][2*c], x11 = ll1[2*r+1][2*c+1];
            float alo = lo0 * x00 + lo1 * x01;
            float ahi = hi0 * x00 + hi1 * x01;
            float blo = lo0 * x10 + lo1 * x11;
            float bhi = hi0 * x10 + hi1 * x11;
            ll2[r][c] = lo0 * alo + lo1 * blo;
            lh[c]     = hi0 * alo + hi1 * blo;
            hl[c]     = lo0 * ahi + lo1 * bhi;
            hh[c]     = hi0 * ahi + hi1 * bhi;
        }
        *((float2*)(lh2 + r * 64)) = make_float2(lh[0], lh[1]);
        *((float2*)(hl2 + r * 64)) = make_float2(hl[0], hl[1]);
        *((float2*)(hh2 + r * 64)) = make_float2(hh[0], hh[1]);
    }

    // ---------------- level 3 ----------------
    {
        float x00 = ll2[0][0], x01 = ll2[0][1];
        float x10 = ll2[1][0], x11 = ll2[1][1];
        float alo = lo0 * x00 + lo1 * x01;
        float ahi = hi0 * x00 + hi1 * x01;
        float blo = lo0 * x10 + lo1 * x11;
        float bhi = hi0 * x10 + hi1 * x11;
        size_t o3 = (size_t)bc * 1024u + by * 32u + bx;
        out[o3]             = lo0 * alo + lo1 * blo;  // l3 (final approx)
        out[1048576u + o3]  = hi0 * alo + hi1 * blo;  // lh3
        out[2097152u + o3]  = lo0 * ahi + lo1 * bhi;  // hl3
        out[3145728u + o3]  = hi0 * ahi + hi1 * bhi;  // hh3
    }
}

extern "C" void kernel_launch(void* const* d_in, const int* in_sizes, int n_in,
                              void* d_out, int out_size) {
    const float* x      = (const float*)d_in[0];
    const float* dec_lo = (const float*)d_in[1];
    const float* dec_hi = (const float*)d_in[2];
    float* out = (float*)d_out;

    // 16*64 planes * 32*32 blocks of 8x8 = 1,048,576 threads; 512/block
    dwt3_fused_kernel<<<2048, 512>>>(x, dec_lo, dec_hi, out);
}